// round 9
// baseline (speedup 1.0000x reference)
#include <cuda_runtime.h>
#include <math.h>

// Problem constants
#define Bz 4
#define Lz 2048
#define Dm 1024
#define Hh 16
#define HD 64
#define Mrows (Bz*Lz)   // 8192
#define EPSLN 1e-5f

// Scratch (static device globals — allocation-free)
__device__ float g_q[(size_t)Mrows * Dm];
__device__ float g_k[(size_t)Mrows * Dm];
__device__ float g_v[(size_t)Mrows * Dm];
__device__ float g_attn[(size_t)Mrows * Dm];
__device__ float g_proj[(size_t)Mrows * Dm];

// ---------------------------------------------------------------------------
// Helpers: cp.async + tf32 mma (fp32 bits fed directly; HW truncates mantissa)
// ---------------------------------------------------------------------------
__device__ __forceinline__ unsigned su32(const void* p) {
    return (unsigned)__cvta_generic_to_shared(p);
}
#define CPA(dst, src) asm volatile("cp.async.cg.shared.global [%0], [%1], 16;\n" :: "r"(dst), "l"(src))
#define CPC() asm volatile("cp.async.commit_group;\n" ::: "memory")
template <int N> __device__ __forceinline__ void cpw() {
    asm volatile("cp.async.wait_group %0;\n" :: "n"(N) : "memory");
}
#define U(x) __float_as_uint(x)

__device__ __forceinline__ void mma_tf32(float c[4], const unsigned a[4],
                                         const unsigned b[2]) {
    asm volatile(
        "mma.sync.aligned.m16n8k8.row.col.f32.tf32.tf32.f32 "
        "{%0,%1,%2,%3},{%4,%5,%6,%7},{%8,%9},{%0,%1,%2,%3};"
        : "+f"(c[0]), "+f"(c[1]), "+f"(c[2]), "+f"(c[3])
        : "r"(a[0]), "r"(a[1]), "r"(a[2]), "r"(a[3]), "r"(b[0]), "r"(b[1]));
}

// ---------------------------------------------------------------------------
// GEMM: C[M,N] = A[M,K] @ W[K,N] + bias[N]   (M=8192, N=K=1024)
// CTA 128x256, BK=32, 8 warps (2x4 of 64x64 warp tiles), 3-stage cp.async.
// A smem [m][k] (16B-chunk swizzle: kc ^ (m&7));  per-stage 4096 floats.
// B smem [k][n] (chunk swizzle: nc ^ ((k&3)<<1)); per-stage 8192 floats.
// Fragment LDS patterns conflict-free (verified: 32 distinct banks each).
// ---------------------------------------------------------------------------
#define GA_ST 4096
#define GB_ST 8192

__device__ __forceinline__ void gemm_issue(float* As, float* Bs,
                                           const float* __restrict__ A,
                                           const float* __restrict__ W,
                                           int m0, int n0, int k0) {
    const int tid = threadIdx.x;
#pragma unroll
    for (int it = 0; it < 4; it++) {
        int f = tid + it * 256;          // 0..1023 chunks of A tile (128x8)
        int m = f >> 3;
        int kc = f & 7;
        CPA(su32(As + m * 32 + ((kc ^ (m & 7)) << 2)),
            A + (size_t)(m0 + m) * Dm + k0 + kc * 4);
    }
#pragma unroll
    for (int it = 0; it < 8; it++) {
        int f = tid + it * 256;          // 0..2047 chunks of B tile (32x64)
        int k = f >> 6;                  // 0..31
        int nc = f & 63;                 // 0..63
        CPA(su32(Bs + k * 256 + ((nc ^ ((k & 3) << 1)) << 2)),
            W + (size_t)(k0 + k) * Dm + n0 + nc * 4);
    }
}

__device__ __forceinline__ void gemm_body(const float* __restrict__ A,
                                          const float* __restrict__ W,
                                          const float* __restrict__ bias,
                                          float* __restrict__ C) {
    extern __shared__ float sg[];
    float* As = sg;                // 3 stages x 128x32
    float* Bs = sg + 3 * GA_ST;    // 3 stages x 32x256

    const int tid = threadIdx.x;
    const int lane = tid & 31;
    const int warp = tid >> 5;
    const int gid = lane >> 2;
    const int tig = lane & 3;
    const int wm = (warp >> 2) * 64;   // 0 or 64
    const int wn = (warp & 3) * 64;    // 0,64,128,192
    const int m0 = blockIdx.y * 128;
    const int n0 = blockIdx.x * 256;

    float c[4][8][4];
#pragma unroll
    for (int mt = 0; mt < 4; mt++)
#pragma unroll
        for (int nt = 0; nt < 8; nt++)
#pragma unroll
            for (int r = 0; r < 4; r++) c[mt][nt][r] = 0.f;

    gemm_issue(As, Bs, A, W, m0, n0, 0); CPC();
    gemm_issue(As + GA_ST, Bs + GB_ST, A, W, m0, n0, 32); CPC();

    const int KT = Dm / 32;
    for (int kt = 0; kt < KT; kt++) {
        if (kt + 2 < KT) cpw<1>(); else cpw<0>();
        __syncthreads();
        if (kt + 2 < KT) {
            int st = (kt + 2) % 3;
            gemm_issue(As + st * GA_ST, Bs + st * GB_ST, A, W, m0, n0, (kt + 2) * 32);
            CPC();
        }
        const float* Ax = As + (kt % 3) * GA_ST;
        const float* Bx = Bs + (kt % 3) * GB_ST;

#pragma unroll
        for (int ks = 0; ks < 4; ks++) {
            const int kA = ks * 8 + tig;
            unsigned af[4][4], bf[8][2];
#pragma unroll
            for (int mt = 0; mt < 4; mt++) {
                int m = wm + 16 * mt + gid;
                int c0 = ((2 * ks) ^ (m & 7)) << 2;
                int c1 = ((2 * ks + 1) ^ (m & 7)) << 2;
                af[mt][0] = U(Ax[m * 32 + c0 + tig]);
                af[mt][1] = U(Ax[(m + 8) * 32 + c0 + tig]);
                af[mt][2] = U(Ax[m * 32 + c1 + tig]);
                af[mt][3] = U(Ax[(m + 8) * 32 + c1 + tig]);
            }
#pragma unroll
            for (int nt = 0; nt < 8; nt++) {
                int n = wn + 8 * nt + gid;
                int cc = (((n >> 2) ^ (tig << 1)) << 2) + (n & 3);
                bf[nt][0] = U(Bx[kA * 256 + cc]);
                bf[nt][1] = U(Bx[(kA + 4) * 256 + cc]);
            }
#pragma unroll
            for (int mt = 0; mt < 4; mt++)
#pragma unroll
                for (int nt = 0; nt < 8; nt++)
                    mma_tf32(c[mt][nt], af[mt], bf[nt]);
        }
        // no trailing sync: the barrier at the next iteration's top orders
        // this stage's reads before its buffer is re-issued (kt+3 overwrites
        // stage kt%3 only after all warps passed that barrier).
    }

#pragma unroll
    for (int mt = 0; mt < 4; mt++) {
        int m = m0 + wm + 16 * mt + gid;
#pragma unroll
        for (int nt = 0; nt < 8; nt++) {
            int n = n0 + wn + 8 * nt + 2 * tig;
            float2 bb = *(const float2*)&bias[n];
            *(float2*)&C[(size_t)m * Dm + n] =
                make_float2(c[mt][nt][0] + bb.x, c[mt][nt][1] + bb.y);
            *(float2*)&C[(size_t)(m + 8) * Dm + n] =
                make_float2(c[mt][nt][2] + bb.x, c[mt][nt][3] + bb.y);
        }
    }
}

__global__ __launch_bounds__(256, 1)
void gemm_qkv(const float* __restrict__ x,
              const float* __restrict__ Wq, const float* __restrict__ bq,
              const float* __restrict__ Wk, const float* __restrict__ bk,
              const float* __restrict__ Wv, const float* __restrict__ bv,
              float* __restrict__ q, float* __restrict__ k, float* __restrict__ v) {
    const int z = blockIdx.z;
    const float* W = (z == 0) ? Wq : ((z == 1) ? Wk : Wv);
    const float* bb = (z == 0) ? bq : ((z == 1) ? bk : bv);
    float* C = (z == 0) ? q : ((z == 1) ? k : v);
    gemm_body(x, W, bb, C);
}

__global__ __launch_bounds__(256, 1)
void gemm_one(const float* __restrict__ A, const float* __restrict__ W,
              const float* __restrict__ b, float* __restrict__ C) {
    gemm_body(A, W, b, C);
}

// ---------------------------------------------------------------------------
// Flash attention, tensor cores, double-buffered K AND V (cp.async).
// One CTA per (b, h, 128-q-row tile): 8 warps, each owns 16 query rows.
// Only 2 __syncthreads per KV tile (cp.async visibility); the P tile is
// warp-private (rows r0/r1 belong to one warp) -> __syncwarp only.
// KV swizzle (16B chunks): chunk' = chunk ^ SWZ3(row); Ps: chunk ^ (row&7).
// ---------------------------------------------------------------------------
#define SWZ3(r) (((((r) >> 2) & 1)) | ((((r) & 1)) << 1) | (((((r) >> 1) & 1)) << 2))
#define KV_ST 4096

__device__ __forceinline__ void issue_kv(float* buf, const float* __restrict__ src) {
    const int tid = threadIdx.x;
#pragma unroll
    for (int it = 0; it < 4; it++) {
        int f = tid + it * 256;          // 0..1023 chunks (64x16)
        int r = f >> 4;
        int cc = f & 15;
        CPA(su32(buf + r * 64 + ((cc ^ SWZ3(r)) << 2)),
            src + (size_t)r * Dm + cc * 4);
    }
}

__global__ __launch_bounds__(256, 1)
void attn_tc(const float* __restrict__ Q, const float* __restrict__ K,
             const float* __restrict__ V, float* __restrict__ O) {
    extern __shared__ float sa[];
    float* Kb = sa;                 // 2 stages x 64x64
    float* Vb = sa + 2 * KV_ST;     // 2 stages x 64x64
    float* Ps = sa + 4 * KV_ST;     // 128x64 (Q staging, then P tiles)

    const int tid = threadIdx.x;
    const int lane = tid & 31;
    const int warp = tid >> 5;
    const int gid = lane >> 2;
    const int tig = lane & 3;
    const int q0 = blockIdx.x * 128;
    const int h = blockIdx.y;
    const int b = blockIdx.z;
    const size_t base = (size_t)b * Lz * Dm + (size_t)h * HD;

    // Prologue: async-load Q (128x64), K(0), V(0)
#pragma unroll
    for (int it = 0; it < 8; it++) {
        int f = tid + it * 256;
        int r = f >> 4;
        int cc = f & 15;
        CPA(su32(Ps + r * 64 + ((cc ^ (r & 7)) << 2)),
            Q + base + (size_t)(q0 + r) * Dm + cc * 4);
    }
    CPC();
    issue_kv(Kb, K + base); CPC();
    issue_kv(Vb, V + base); CPC();

    cpw<2>();           // Q landed (K0/V0 may be in flight)
    __syncthreads();

    // Q fragments -> registers, scaled by 1/sqrt(HD)=0.125 (warp-private rows)
    const int r0 = warp * 16 + gid;
    const int r1 = r0 + 8;
    const int sw0 = r0 & 7;
    const int sw1 = r1 & 7;
    unsigned qf[8][4];
#pragma unroll
    for (int ks = 0; ks < 8; ks++) {
        qf[ks][0] = U(0.125f * Ps[r0 * 64 + (((2 * ks) ^ sw0) << 2) + tig]);
        qf[ks][1] = U(0.125f * Ps[r1 * 64 + (((2 * ks) ^ sw1) << 2) + tig]);
        qf[ks][2] = U(0.125f * Ps[r0 * 64 + (((2 * ks + 1) ^ sw0) << 2) + tig]);
        qf[ks][3] = U(0.125f * Ps[r1 * 64 + (((2 * ks + 1) ^ sw1) << 2) + tig]);
    }

    float o[8][4];
#pragma unroll
    for (int nt = 0; nt < 8; nt++)
#pragma unroll
        for (int r = 0; r < 4; r++) o[nt][r] = 0.f;
    float mrun[2] = {-1e30f, -1e30f};
    float lrun[2] = {0.f, 0.f};

    const int NT = Lz / 64;
    // Group invariant at loop top: outstanding = [K(t), V(t)]
    for (int t = 0; t < NT; t++) {
        cpw<1>();               // K(t) visible (V(t) may be in flight)
        __syncthreads();
        if (t + 1 < NT) {       // prefetch K(t+1) into the other stage
            issue_kv(Kb + ((t + 1) & 1) * KV_ST,
                     K + base + (size_t)(t + 1) * 64 * Dm);
            CPC();
        }
        const float* Kx = Kb + (t & 1) * KV_ST;
        const float* Vx = Vb + (t & 1) * KV_ST;

        // S = Q @ K^T
        float s[8][4];
#pragma unroll
        for (int nt = 0; nt < 8; nt++)
#pragma unroll
            for (int r = 0; r < 4; r++) s[nt][r] = 0.f;
#pragma unroll
        for (int ks = 0; ks < 8; ks++) {
#pragma unroll
            for (int nt = 0; nt < 8; nt++) {
                int key = nt * 8 + gid;
                int sw = SWZ3(key);
                unsigned bf[2];
                bf[0] = U(Kx[key * 64 + (((2 * ks) ^ sw) << 2) + tig]);
                bf[1] = U(Kx[key * 64 + (((2 * ks + 1) ^ sw) << 2) + tig]);
                mma_tf32(s[nt], qf[ks], bf);
            }
        }

        // Online softmax (registers; row stats via quad shuffles)
#pragma unroll
        for (int r = 0; r < 2; r++) {
            float mx = mrun[r];
#pragma unroll
            for (int nt = 0; nt < 8; nt++) {
                mx = fmaxf(mx, s[nt][2 * r]);
                mx = fmaxf(mx, s[nt][2 * r + 1]);
            }
            mx = fmaxf(mx, __shfl_xor_sync(0xffffffffu, mx, 1));
            mx = fmaxf(mx, __shfl_xor_sync(0xffffffffu, mx, 2));
            float sumv = 0.f;
#pragma unroll
            for (int nt = 0; nt < 8; nt++) {
                float p0 = __expf(s[nt][2 * r] - mx);
                float p1 = __expf(s[nt][2 * r + 1] - mx);
                s[nt][2 * r] = p0;
                s[nt][2 * r + 1] = p1;
                sumv += p0 + p1;
            }
            sumv += __shfl_xor_sync(0xffffffffu, sumv, 1);
            sumv += __shfl_xor_sync(0xffffffffu, sumv, 2);
            float sc = __expf(mrun[r] - mx);
            lrun[r] = lrun[r] * sc + sumv;
            mrun[r] = mx;
#pragma unroll
            for (int nt = 0; nt < 8; nt++) {
                o[nt][2 * r] *= sc;
                o[nt][2 * r + 1] *= sc;
            }
        }

        // Write P (warp-private rows; raw fp32 bits, mma truncates)
#pragma unroll
        for (int nt = 0; nt < 8; nt++) {
            int cb = nt * 8 + 2 * tig;
            int ch = cb >> 2, wi = cb & 3;
            *(float2*)&Ps[r0 * 64 + ((ch ^ sw0) << 2) + wi] =
                make_float2(s[nt][0], s[nt][1]);
            *(float2*)&Ps[r1 * 64 + ((ch ^ sw1) << 2) + wi] =
                make_float2(s[nt][2], s[nt][3]);
        }
        __syncwarp();

        if (t + 1 < NT) cpw<1>(); else cpw<0>();   // V(t) visible
        __syncthreads();
        if (t + 1 < NT) {       // prefetch V(t+1)
            issue_kv(Vb + ((t + 1) & 1) * KV_ST,
                     V + base + (size_t)(t + 1) * 64 * Dm);
            CPC();
        }

        // O += P @ V
#pragma unroll
        for (int ks = 0; ks < 8; ks++) {
            unsigned af[4];
            af[0] = U(Ps[r0 * 64 + (((2 * ks) ^ sw0) << 2) + tig]);
            af[1] = U(Ps[r1 * 64 + (((2 * ks) ^ sw1) << 2) + tig]);
            af[2] = U(Ps[r0 * 64 + (((2 * ks + 1) ^ sw0) << 2) + tig]);
            af[3] = U(Ps[r1 * 64 + (((2 * ks + 1) ^ sw1) << 2) + tig]);
            int key0 = ks * 8 + tig;
            int swk0 = SWZ3(key0), swk1 = SWZ3(key0 + 4);
#pragma unroll
            for (int nt = 0; nt < 8; nt++) {
                int dd = nt * 8 + gid;
                int ch = dd >> 2, wi = dd & 3;
                unsigned bf[2];
                bf[0] = U(Vx[key0 * 64 + ((ch ^ swk0) << 2) + wi]);
                bf[1] = U(Vx[(key0 + 4) * 64 + ((ch ^ swk1) << 2) + wi]);
                mma_tf32(o[nt], af, bf);
            }
        }
        // no trailing sync: next iteration's barrier orders PV reads before
        // V(t+2) overwrites this stage.
    }

    // Epilogue: normalize + store
#pragma unroll
    for (int r = 0; r < 2; r++) {
        float inv = 1.0f / lrun[r];
        int row = q0 + warp * 16 + gid + 8 * r;
#pragma unroll
        for (int nt = 0; nt < 8; nt++) {
            int col = nt * 8 + 2 * tig;
            *(float2*)&O[base + (size_t)row * Dm + col] =
                make_float2(o[nt][2 * r] * inv, o[nt][2 * r + 1] * inv);
        }
    }
}

// ---------------------------------------------------------------------------
// Residual + LayerNorm
// ---------------------------------------------------------------------------
__global__ __launch_bounds__(256)
void resid_ln(const float* __restrict__ x, const float* __restrict__ proj,
              const float* __restrict__ gamma, const float* __restrict__ beta,
              float* __restrict__ out) {
    __shared__ float red1[8];
    __shared__ float red2[8];
    const int row = blockIdx.x;
    const int t = threadIdx.x;
    const float* xr = x + (size_t)row * Dm;
    const float* pr = proj + (size_t)row * Dm;
    float* outr = out + (size_t)row * Dm;

    float v[4];
    float s = 0.f;
#pragma unroll
    for (int i = 0; i < 4; i++) {
        int c = t + 256 * i;
        v[i] = xr[c] + pr[c];
        s += v[i];
    }
#pragma unroll
    for (int off = 16; off > 0; off >>= 1) s += __shfl_xor_sync(~0u, s, off);
    if ((t & 31) == 0) red1[t >> 5] = s;
    __syncthreads();
    float mu = 0.f;
#pragma unroll
    for (int i = 0; i < 8; i++) mu += red1[i];
    mu *= (1.0f / Dm);

    float vs = 0.f;
#pragma unroll
    for (int i = 0; i < 4; i++) {
        float d = v[i] - mu;
        vs += d * d;
    }
#pragma unroll
    for (int off = 16; off > 0; off >>= 1) vs += __shfl_xor_sync(~0u, vs, off);
    if ((t & 31) == 0) red2[t >> 5] = vs;
    __syncthreads();
    float var = 0.f;
#pragma unroll
    for (int i = 0; i < 8; i++) var += red2[i];
    var *= (1.0f / Dm);
    float rstd = rsqrtf(var + EPSLN);

#pragma unroll
    for (int i = 0; i < 4; i++) {
        int c = t + 256 * i;
        outr[c] = (v[i] - mu) * rstd * gamma[c] + beta[c];
    }
}

// ---------------------------------------------------------------------------
extern "C" void kernel_launch(void* const* d_in, const int* in_sizes, int n_in,
                              void* d_out, int out_size) {
    const float* x     = (const float*)d_in[0];
    const float* Wq    = (const float*)d_in[1];
    const float* bq    = (const float*)d_in[2];
    const float* Wk    = (const float*)d_in[3];
    const float* bk    = (const float*)d_in[4];
    const float* Wv    = (const float*)d_in[5];
    const float* bv    = (const float*)d_in[6];
    const float* Wo    = (const float*)d_in[7];
    const float* bo    = (const float*)d_in[8];
    const float* gamma = (const float*)d_in[9];
    const float* beta  = (const float*)d_in[10];
    float* out = (float*)d_out;

    float *q, *k, *v, *attn, *proj;
    cudaGetSymbolAddress((void**)&q,    g_q);
    cudaGetSymbolAddress((void**)&k,    g_k);
    cudaGetSymbolAddress((void**)&v,    g_v);
    cudaGetSymbolAddress((void**)&attn, g_attn);
    cudaGetSymbolAddress((void**)&proj, g_proj);

    const int gemm_smem = 3 * (GA_ST + GB_ST) * (int)sizeof(float);   // 144 KB
    const int attn_smem = (4 * KV_ST + 128 * 64) * (int)sizeof(float); // 96 KB
    cudaFuncSetAttribute(gemm_qkv, cudaFuncAttributeMaxDynamicSharedMemorySize, gemm_smem);
    cudaFuncSetAttribute(gemm_one, cudaFuncAttributeMaxDynamicSharedMemorySize, gemm_smem);
    cudaFuncSetAttribute(attn_tc,  cudaFuncAttributeMaxDynamicSharedMemorySize, attn_smem);

    dim3 qkvgrid(Dm / 256, Mrows / 128, 3);   // (4, 64, 3)
    gemm_qkv<<<qkvgrid, 256, gemm_smem>>>(x, Wq, bq, Wk, bk, Wv, bv, q, k, v);

    dim3 agrid(Lz / 128, Hh, Bz);             // (16, 16, 4)
    attn_tc<<<agrid, 256, attn_smem>>>(q, k, v, attn);

    dim3 ogrid(Dm / 256, Mrows / 128);        // (4, 64)
    gemm_one<<<ogrid, 256, gemm_smem>>>(attn, Wo, bo, proj);

    resid_ln<<<Mrows, 256>>>(x, proj, gamma, beta, out);
}

// round 14
// speedup vs baseline: 1.3395x; 1.3395x over previous
#include <cuda_runtime.h>
#include <cuda_bf16.h>
#include <math.h>

// Problem constants
#define Bz 4
#define Lz 2048
#define Dm 1024
#define Hh 16
#define HD 64
#define Mrows (Bz*Lz)   // 8192
#define EPSLN 1e-5f

// Scratch (static device globals — allocation-free)
__device__ __nv_bfloat16 g_qb[(size_t)Mrows * Dm];   // Q, pre-scaled 0.125, [M][D]
__device__ __nv_bfloat16 g_kb[(size_t)Mrows * Dm];   // K, [M][D]
__device__ __nv_bfloat16 g_vt[(size_t)Mrows * Dm];   // V^T, [b][h][d][L]
__device__ float g_attn[(size_t)Mrows * Dm];
__device__ float g_proj[(size_t)Mrows * Dm];

// ---------------------------------------------------------------------------
// Helpers
// ---------------------------------------------------------------------------
__device__ __forceinline__ unsigned su32(const void* p) {
    return (unsigned)__cvta_generic_to_shared(p);
}
#define CPA(dst, src) asm volatile("cp.async.cg.shared.global [%0], [%1], 16;\n" :: "r"(dst), "l"(src))
#define CPC() asm volatile("cp.async.commit_group;\n" ::: "memory")
template <int N> __device__ __forceinline__ void cpw() {
    asm volatile("cp.async.wait_group %0;\n" :: "n"(N) : "memory");
}
#define U(x) __float_as_uint(x)

__device__ __forceinline__ void mma_tf32(float c[4], const unsigned a[4],
                                         const unsigned b[2]) {
    asm volatile(
        "mma.sync.aligned.m16n8k8.row.col.f32.tf32.tf32.f32 "
        "{%0,%1,%2,%3},{%4,%5,%6,%7},{%8,%9},{%0,%1,%2,%3};"
        : "+f"(c[0]), "+f"(c[1]), "+f"(c[2]), "+f"(c[3])
        : "r"(a[0]), "r"(a[1]), "r"(a[2]), "r"(a[3]), "r"(b[0]), "r"(b[1]));
}

__device__ __forceinline__ void mma_bf16(float c[4], const unsigned a[4],
                                         const unsigned b[2]) {
    asm volatile(
        "mma.sync.aligned.m16n8k16.row.col.f32.bf16.bf16.f32 "
        "{%0,%1,%2,%3},{%4,%5,%6,%7},{%8,%9},{%0,%1,%2,%3};"
        : "+f"(c[0]), "+f"(c[1]), "+f"(c[2]), "+f"(c[3])
        : "r"(a[0]), "r"(a[1]), "r"(a[2]), "r"(a[3]), "r"(b[0]), "r"(b[1]));
}

// pack two floats into bf16x2: lo -> low half (lower address), hi -> high half
__device__ __forceinline__ unsigned packbf(float lo, float hi) {
    unsigned r;
    asm("cvt.rn.bf16x2.f32 %0, %1, %2;" : "=r"(r) : "f"(hi), "f"(lo));
    return r;
}

// ---------------------------------------------------------------------------
// GEMM: C[M,N] = A[M,K] @ W[K,N] + bias[N]   (tf32, M=8192, N=K=1024)
// CTA 128x256, BK=32, 8 warps (2x4 of 64x64 warp tiles), 3-stage cp.async.
// Epilogue MODE: 0 = fp32 [M][N];  1 = bf16 [M][N] scaled 0.125 (Q);
//                2 = bf16 [M][N] (K);  3 = bf16 transposed [b][h][d][L] (V).
// ---------------------------------------------------------------------------
#define GA_ST 4096
#define GB_ST 8192

__device__ __forceinline__ void gemm_issue(float* As, float* Bs,
                                           const float* __restrict__ A,
                                           const float* __restrict__ W,
                                           int m0, int n0, int k0) {
    const int tid = threadIdx.x;
#pragma unroll
    for (int it = 0; it < 4; it++) {
        int f = tid + it * 256;
        int m = f >> 3;
        int kc = f & 7;
        CPA(su32(As + m * 32 + ((kc ^ (m & 7)) << 2)),
            A + (size_t)(m0 + m) * Dm + k0 + kc * 4);
    }
#pragma unroll
    for (int it = 0; it < 8; it++) {
        int f = tid + it * 256;
        int k = f >> 6;
        int nc = f & 63;
        CPA(su32(Bs + k * 256 + ((nc ^ ((k & 3) << 1)) << 2)),
            W + (size_t)(k0 + k) * Dm + n0 + nc * 4);
    }
}

template <int MODE>
__device__ __forceinline__ void gemm_body(const float* __restrict__ A,
                                          const float* __restrict__ W,
                                          const float* __restrict__ bias,
                                          float* __restrict__ Cf,
                                          __nv_bfloat16* __restrict__ Cb) {
    extern __shared__ float sg[];
    float* As = sg;
    float* Bs = sg + 3 * GA_ST;

    const int tid = threadIdx.x;
    const int lane = tid & 31;
    const int warp = tid >> 5;
    const int gid = lane >> 2;
    const int tig = lane & 3;
    const int wm = (warp >> 2) * 64;
    const int wn = (warp & 3) * 64;
    const int m0 = blockIdx.y * 128;
    const int n0 = blockIdx.x * 256;

    float c[4][8][4];
#pragma unroll
    for (int mt = 0; mt < 4; mt++)
#pragma unroll
        for (int nt = 0; nt < 8; nt++)
#pragma unroll
            for (int r = 0; r < 4; r++) c[mt][nt][r] = 0.f;

    gemm_issue(As, Bs, A, W, m0, n0, 0); CPC();
    gemm_issue(As + GA_ST, Bs + GB_ST, A, W, m0, n0, 32); CPC();

    const int KT = Dm / 32;
    for (int kt = 0; kt < KT; kt++) {
        if (kt + 2 < KT) cpw<1>(); else cpw<0>();
        __syncthreads();
        if (kt + 2 < KT) {
            int st = (kt + 2) % 3;
            gemm_issue(As + st * GA_ST, Bs + st * GB_ST, A, W, m0, n0, (kt + 2) * 32);
            CPC();
        }
        const float* Ax = As + (kt % 3) * GA_ST;
        const float* Bx = Bs + (kt % 3) * GB_ST;

#pragma unroll
        for (int ks = 0; ks < 4; ks++) {
            const int kA = ks * 8 + tig;
            unsigned af[4][4], bf[8][2];
#pragma unroll
            for (int mt = 0; mt < 4; mt++) {
                int m = wm + 16 * mt + gid;
                int c0 = ((2 * ks) ^ (m & 7)) << 2;
                int c1 = ((2 * ks + 1) ^ (m & 7)) << 2;
                af[mt][0] = U(Ax[m * 32 + c0 + tig]);
                af[mt][1] = U(Ax[(m + 8) * 32 + c0 + tig]);
                af[mt][2] = U(Ax[m * 32 + c1 + tig]);
                af[mt][3] = U(Ax[(m + 8) * 32 + c1 + tig]);
            }
#pragma unroll
            for (int nt = 0; nt < 8; nt++) {
                int n = wn + 8 * nt + gid;
                int cc = (((n >> 2) ^ (tig << 1)) << 2) + (n & 3);
                bf[nt][0] = U(Bx[kA * 256 + cc]);
                bf[nt][1] = U(Bx[(kA + 4) * 256 + cc]);
            }
#pragma unroll
            for (int mt = 0; mt < 4; mt++)
#pragma unroll
                for (int nt = 0; nt < 8; nt++)
                    mma_tf32(c[mt][nt], af[mt], bf[nt]);
        }
    }

    const float scale = (MODE == 1) ? 0.125f : 1.0f;
#pragma unroll
    for (int mt = 0; mt < 4; mt++) {
        int m = m0 + wm + 16 * mt + gid;
#pragma unroll
        for (int nt = 0; nt < 8; nt++) {
            int n = n0 + wn + 8 * nt + 2 * tig;
            float2 bb = *(const float2*)&bias[n];
            float v0 = c[mt][nt][0] + bb.x, v1 = c[mt][nt][1] + bb.y;
            float v2 = c[mt][nt][2] + bb.x, v3 = c[mt][nt][3] + bb.y;
            if (MODE == 0) {
                *(float2*)&Cf[(size_t)m * Dm + n] = make_float2(v0, v1);
                *(float2*)&Cf[(size_t)(m + 8) * Dm + n] = make_float2(v2, v3);
            } else if (MODE == 1 || MODE == 2) {
                *(unsigned*)&Cb[(size_t)m * Dm + n] = packbf(v0 * scale, v1 * scale);
                *(unsigned*)&Cb[(size_t)(m + 8) * Dm + n] = packbf(v2 * scale, v3 * scale);
            } else {   // MODE 3: V transposed -> [b][h][d][L]
                int bidx = m >> 11, tok = m & 2047;
                int h = n >> 6, d = n & 63;
                size_t r0 = ((size_t)(bidx * Hh + h) * HD + d) * Lz;
                size_t r1 = ((size_t)(bidx * Hh + h) * HD + (d + 1)) * Lz;
                Cb[r0 + tok]     = __float2bfloat16(v0);
                Cb[r1 + tok]     = __float2bfloat16(v1);
                Cb[r0 + tok + 8] = __float2bfloat16(v2);
                Cb[r1 + tok + 8] = __float2bfloat16(v3);
            }
        }
    }
}

__global__ __launch_bounds__(256, 1)
void gemm_qkv(const float* __restrict__ x,
              const float* __restrict__ Wq, const float* __restrict__ bq,
              const float* __restrict__ Wk, const float* __restrict__ bk,
              const float* __restrict__ Wv, const float* __restrict__ bv,
              __nv_bfloat16* __restrict__ qb, __nv_bfloat16* __restrict__ kb,
              __nv_bfloat16* __restrict__ vt) {
    const int z = blockIdx.z;
    if (z == 0)      gemm_body<1>(x, Wq, bq, nullptr, qb);
    else if (z == 1) gemm_body<2>(x, Wk, bk, nullptr, kb);
    else             gemm_body<3>(x, Wv, bv, nullptr, vt);
}

__global__ __launch_bounds__(256, 1)
void gemm_one(const float* __restrict__ A, const float* __restrict__ W,
              const float* __restrict__ b, float* __restrict__ C) {
    gemm_body<0>(A, W, b, C, nullptr);
}

// ---------------------------------------------------------------------------
// Flash attention, bf16 tensor cores (m16n8k16), fp32 accum/softmax.
// One CTA per (b, h, 128-q-row tile): 8 warps, each owns 16 query rows.
// Smem tiles are bf16, row-major [row][64], stored as 32 words/row with one
// uniform swizzle: word w in chunk c (16B=4 words) -> c' = c ^ (row&7).
// Verified conflict-free for Q/K/P/V^T fragment reads and P writes.
// K and V^T double-buffered via cp.async; Q staging buffer reused for P
// (both warp-private row ranges -> no extra barriers).
// ---------------------------------------------------------------------------
#define KV_W 2048    // words per 64x64 bf16 tile

__device__ __forceinline__ void issue_kv64(unsigned* buf,
                                           const __nv_bfloat16* __restrict__ src,
                                           int row_stride) {
    const int tid = threadIdx.x;
#pragma unroll
    for (int it = 0; it < 2; it++) {
        int f = tid + it * 256;          // 0..511 chunks (64 rows x 8)
        int r = f >> 3;
        int c = f & 7;
        CPA(su32(buf + r * 32 + ((c ^ (r & 7)) << 2)),
            src + (size_t)r * row_stride + c * 8);
    }
}

__global__ __launch_bounds__(256, 2)
void attn_tc(const __nv_bfloat16* __restrict__ Qb,
             const __nv_bfloat16* __restrict__ Kb,
             const __nv_bfloat16* __restrict__ Vt,
             float* __restrict__ O) {
    extern __shared__ unsigned sa_u[];
    unsigned* Kbuf = sa_u;                // 2 stages x 2048 words
    unsigned* Vbuf = sa_u + 2 * KV_W;     // 2 stages x 2048 words
    unsigned* QP   = sa_u + 4 * KV_W;     // 128 x 32 words (Q staging, then P)

    const int tid = threadIdx.x;
    const int lane = tid & 31;
    const int warp = tid >> 5;
    const int gid = lane >> 2;
    const int tig = lane & 3;
    const int q0 = blockIdx.x * 128;
    const int h = blockIdx.y;
    const int b = blockIdx.z;
    const size_t base_qk = (size_t)(b * Lz) * Dm + h * HD;            // [tok][feat]
    const size_t base_v  = (size_t)(b * Hh + h) * HD * Lz;            // [d][tok]

    // Prologue: async-load Q (128x64 bf16), K(0), V^T(0)
#pragma unroll
    for (int it = 0; it < 4; it++) {
        int f = tid + it * 256;          // 0..1023 chunks
        int r = f >> 3;                  // 0..127
        int c = f & 7;
        CPA(su32(QP + r * 32 + ((c ^ (r & 7)) << 2)),
            Qb + base_qk + (size_t)(q0 + r) * Dm + c * 8);
    }
    CPC();
    issue_kv64(Kbuf, Kb + base_qk, Dm); CPC();
    issue_kv64(Vbuf, Vt + base_v, Lz); CPC();

    cpw<2>();            // Q landed
    __syncthreads();

    // Q fragments (bf16 pairs, pre-scaled in GEMM) — warp-private rows
    const int r0 = warp * 16 + gid;
    const int r1 = r0 + 8;
    const int sw0 = r0 & 7;
    const int sw1 = r1 & 7;
    unsigned qf[4][4];
#pragma unroll
    for (int ks = 0; ks < 4; ks++) {
        qf[ks][0] = QP[r0 * 32 + (((2 * ks) ^ sw0) << 2) + tig];
        qf[ks][1] = QP[r1 * 32 + (((2 * ks) ^ sw1) << 2) + tig];
        qf[ks][2] = QP[r0 * 32 + (((2 * ks + 1) ^ sw0) << 2) + tig];
        qf[ks][3] = QP[r1 * 32 + (((2 * ks + 1) ^ sw1) << 2) + tig];
    }

    float o[8][4];
#pragma unroll
    for (int nt = 0; nt < 8; nt++)
#pragma unroll
        for (int r = 0; r < 4; r++) o[nt][r] = 0.f;
    float mrun[2] = {-1e30f, -1e30f};
    float lrun[2] = {0.f, 0.f};

    const int NT = Lz / 64;
    // Loop-top invariant: outstanding cp.async groups = [K(t), V(t)]
    for (int t = 0; t < NT; t++) {
        cpw<1>();                // K(t) visible
        __syncthreads();
        if (t + 1 < NT) {
            issue_kv64(Kbuf + ((t + 1) & 1) * KV_W,
                       Kb + base_qk + (size_t)(t + 1) * 64 * Dm, Dm);
            CPC();
        }
        const unsigned* Kx = Kbuf + (t & 1) * KV_W;
        const unsigned* Vx = Vbuf + (t & 1) * KV_W;

        // S = Q @ K^T   (bf16 mma, fp32 accum)
        float s[8][4];
#pragma unroll
        for (int nt = 0; nt < 8; nt++)
#pragma unroll
            for (int r = 0; r < 4; r++) s[nt][r] = 0.f;
#pragma unroll
        for (int ks = 0; ks < 4; ks++) {
#pragma unroll
            for (int nt = 0; nt < 8; nt++) {
                int key = nt * 8 + gid;
                unsigned bfr[2];
                bfr[0] = Kx[key * 32 + (((2 * ks) ^ (key & 7)) << 2) + tig];
                bfr[1] = Kx[key * 32 + (((2 * ks + 1) ^ (key & 7)) << 2) + tig];
                mma_bf16(s[nt], qf[ks], bfr);
            }
        }

        // Online softmax (fp32 registers; row stats via quad shuffles)
#pragma unroll
        for (int r = 0; r < 2; r++) {
            float mx = mrun[r];
#pragma unroll
            for (int nt = 0; nt < 8; nt++) {
                mx = fmaxf(mx, s[nt][2 * r]);
                mx = fmaxf(mx, s[nt][2 * r + 1]);
            }
            mx = fmaxf(mx, __shfl_xor_sync(0xffffffffu, mx, 1));
            mx = fmaxf(mx, __shfl_xor_sync(0xffffffffu, mx, 2));
            float sumv = 0.f;
#pragma unroll
            for (int nt = 0; nt < 8; nt++) {
                float p0 = __expf(s[nt][2 * r] - mx);
                float p1 = __expf(s[nt][2 * r + 1] - mx);
                s[nt][2 * r] = p0;
                s[nt][2 * r + 1] = p1;
                sumv += p0 + p1;
            }
            sumv += __shfl_xor_sync(0xffffffffu, sumv, 1);
            sumv += __shfl_xor_sync(0xffffffffu, sumv, 2);
            float sc = __expf(mrun[r] - mx);
            lrun[r] = lrun[r] * sc + sumv;
            mrun[r] = mx;
#pragma unroll
            for (int nt = 0; nt < 8; nt++) {
                o[nt][2 * r] *= sc;
                o[nt][2 * r + 1] *= sc;
            }
        }

        // Write P as bf16x2 (warp-private rows)
#pragma unroll
        for (int nt = 0; nt < 8; nt++) {
            QP[r0 * 32 + ((nt ^ sw0) << 2) + tig] = packbf(s[nt][0], s[nt][1]);
            QP[r1 * 32 + ((nt ^ sw1) << 2) + tig] = packbf(s[nt][2], s[nt][3]);
        }
        __syncwarp();

        if (t + 1 < NT) cpw<1>(); else cpw<0>();   // V(t) visible
        __syncthreads();
        if (t + 1 < NT) {
            issue_kv64(Vbuf + ((t + 1) & 1) * KV_W,
                       Vt + base_v + (size_t)(t + 1) * 64, Lz);
            CPC();
        }

        // O += P @ V   (A = P[q][key], B = V^T[d][key] -> B[k=key][n=d])
#pragma unroll
        for (int ks = 0; ks < 4; ks++) {
            unsigned af[4];
            af[0] = QP[r0 * 32 + (((2 * ks) ^ sw0) << 2) + tig];
            af[1] = QP[r1 * 32 + (((2 * ks) ^ sw1) << 2) + tig];
            af[2] = QP[r0 * 32 + (((2 * ks + 1) ^ sw0) << 2) + tig];
            af[3] = QP[r1 * 32 + (((2 * ks + 1) ^ sw1) << 2) + tig];
#pragma unroll
            for (int nt = 0; nt < 8; nt++) {
                int d = nt * 8 + gid;
                unsigned bfr[2];
                bfr[0] = Vx[d * 32 + (((2 * ks) ^ (d & 7)) << 2) + tig];
                bfr[1] = Vx[d * 32 + (((2 * ks + 1) ^ (d & 7)) << 2) + tig];
                mma_bf16(o[nt], af, bfr);
            }
        }
        // no trailing sync: next iteration's barriers order these reads
        // before stage reuse (K(t+2)/V(t+2) land after those barriers).
    }

    // Epilogue: normalize + store fp32
#pragma unroll
    for (int r = 0; r < 2; r++) {
        float inv = 1.0f / lrun[r];
        int row = q0 + warp * 16 + gid + 8 * r;
#pragma unroll
        for (int nt = 0; nt < 8; nt++) {
            int col = nt * 8 + 2 * tig;
            *(float2*)&O[base_qk + (size_t)row * Dm + col] =
                make_float2(o[nt][2 * r] * inv, o[nt][2 * r + 1] * inv);
        }
    }
}

// ---------------------------------------------------------------------------
// Residual + LayerNorm (float4 loads/stores)
// ---------------------------------------------------------------------------
__global__ __launch_bounds__(256)
void resid_ln(const float* __restrict__ x, const float* __restrict__ proj,
              const float* __restrict__ gamma, const float* __restrict__ beta,
              float* __restrict__ out) {
    __shared__ float red1[8];
    __shared__ float red2[8];
    const int row = blockIdx.x;
    const int t = threadIdx.x;
    const float* xr = x + (size_t)row * Dm;
    const float* pr = proj + (size_t)row * Dm;
    float* outr = out + (size_t)row * Dm;

    float4 xv = *(const float4*)&xr[t * 4];
    float4 pv = *(const float4*)&pr[t * 4];
    float v[4] = {xv.x + pv.x, xv.y + pv.y, xv.z + pv.z, xv.w + pv.w};
    float s = v[0] + v[1] + v[2] + v[3];
#pragma unroll
    for (int off = 16; off > 0; off >>= 1) s += __shfl_xor_sync(~0u, s, off);
    if ((t & 31) == 0) red1[t >> 5] = s;
    __syncthreads();
    float mu = 0.f;
#pragma unroll
    for (int i = 0; i < 8; i++) mu += red1[i];
    mu *= (1.0f / Dm);

    float vs = 0.f;
#pragma unroll
    for (int i = 0; i < 4; i++) {
        float d = v[i] - mu;
        vs += d * d;
    }
#pragma unroll
    for (int off = 16; off > 0; off >>= 1) vs += __shfl_xor_sync(~0u, vs, off);
    if ((t & 31) == 0) red2[t >> 5] = vs;
    __syncthreads();
    float var = 0.f;
#pragma unroll
    for (int i = 0; i < 8; i++) var += red2[i];
    var *= (1.0f / Dm);
    float rstd = rsqrtf(var + EPSLN);

    float4 gv = *(const float4*)&gamma[t * 4];
    float4 bv = *(const float4*)&beta[t * 4];
    float4 ov;
    ov.x = (v[0] - mu) * rstd * gv.x + bv.x;
    ov.y = (v[1] - mu) * rstd * gv.y + bv.y;
    ov.z = (v[2] - mu) * rstd * gv.z + bv.z;
    ov.w = (v[3] - mu) * rstd * gv.w + bv.w;
    *(float4*)&outr[t * 4] = ov;
}

// ---------------------------------------------------------------------------
extern "C" void kernel_launch(void* const* d_in, const int* in_sizes, int n_in,
                              void* d_out, int out_size) {
    const float* x     = (const float*)d_in[0];
    const float* Wq    = (const float*)d_in[1];
    const float* bq    = (const float*)d_in[2];
    const float* Wk    = (const float*)d_in[3];
    const float* bk    = (const float*)d_in[4];
    const float* Wv    = (const float*)d_in[5];
    const float* bv    = (const float*)d_in[6];
    const float* Wo    = (const float*)d_in[7];
    const float* bo    = (const float*)d_in[8];
    const float* gamma = (const float*)d_in[9];
    const float* beta  = (const float*)d_in[10];
    float* out = (float*)d_out;

    __nv_bfloat16 *qb, *kb, *vt;
    float *attn, *proj;
    cudaGetSymbolAddress((void**)&qb,   g_qb);
    cudaGetSymbolAddress((void**)&kb,   g_kb);
    cudaGetSymbolAddress((void**)&vt,   g_vt);
    cudaGetSymbolAddress((void**)&attn, g_attn);
    cudaGetSymbolAddress((void**)&proj, g_proj);

    const int gemm_smem = 3 * (GA_ST + GB_ST) * (int)sizeof(float);   // 144 KB
    const int attn_smem = (4 * KV_W + 128 * 32) * (int)sizeof(unsigned); // 48 KB
    cudaFuncSetAttribute(gemm_qkv, cudaFuncAttributeMaxDynamicSharedMemorySize, gemm_smem);
    cudaFuncSetAttribute(gemm_one, cudaFuncAttributeMaxDynamicSharedMemorySize, gemm_smem);
    cudaFuncSetAttribute(attn_tc,  cudaFuncAttributeMaxDynamicSharedMemorySize, attn_smem);

    dim3 qkvgrid(Dm / 256, Mrows / 128, 3);   // (4, 64, 3)
    gemm_qkv<<<qkvgrid, 256, gemm_smem>>>(x, Wq, bq, Wk, bk, Wv, bv, qb, kb, vt);

    dim3 agrid(Lz / 128, Hh, Bz);             // (16, 16, 4)
    attn_tc<<<agrid, 256, attn_smem>>>(qb, kb, vt, attn);

    dim3 ogrid(Dm / 256, Mrows / 128);        // (4, 64)
    gemm_one<<<ogrid, 256, gemm_smem>>>(attn, Wo, bo, proj);

    resid_ln<<<Mrows, 256>>>(x, proj, gamma, beta, out);
}